// round 14
// baseline (speedup 1.0000x reference)
#include <cuda_runtime.h>
#include <cuda_fp16.h>
#include <math.h>
#include <stdint.h>

// Problem constants
#define BB    2
#define SS    2048
#define HIDD  2048
#define NHQ   16
#define NHKV  4
#define HDIM  128
#define KD    2048
#define MTOT  (BB*SS)     // 4096

// ---------------------------------------------------------------------------
// Device-global scratch
// ---------------------------------------------------------------------------
__device__ __half g_q16[(size_t)BB*NHQ *SS*HDIM];   // [B][H][S][HD]
__device__ __half g_k16[(size_t)BB*NHKV*SS*HDIM];
__device__ __half g_v16[(size_t)BB*NHKV*SS*HDIM];

__device__ __half g_a16 [(size_t)MTOT*KD];          // x, then y
__device__ __half g_wq16[(size_t)2048*2048];
__device__ __half g_wk16[(size_t)512*2048];
__device__ __half g_wv16[(size_t)512*2048];
__device__ __half g_wo16[(size_t)2048*2048];

// ---------------------------------------------------------------------------
__device__ __forceinline__ uint32_t smem_u32(const void* p) {
    uint32_t a;
    asm("{ .reg .u64 t; cvta.to.shared.u64 t, %1; cvt.u32.u64 %0, t; }"
        : "=r"(a) : "l"(p));
    return a;
}

#define LDM4(r0, r1, r2, r3, addr) \
    asm volatile("ldmatrix.sync.aligned.m8n8.x4.shared.b16 {%0,%1,%2,%3}, [%4];" \
                 : "=r"(r0), "=r"(r1), "=r"(r2), "=r"(r3) : "r"(addr))

#define LDM4T(r0, r1, r2, r3, addr) \
    asm volatile("ldmatrix.sync.aligned.m8n8.x4.trans.shared.b16 {%0,%1,%2,%3}, [%4];" \
                 : "=r"(r0), "=r"(r1), "=r"(r2), "=r"(r3) : "r"(addr))

#define MMA16816(acc, a, b) \
    asm volatile("mma.sync.aligned.m16n8k16.row.col.f32.f16.f16.f32 " \
                 "{%0,%1,%2,%3},{%4,%5,%6,%7},{%8,%9},{%0,%1,%2,%3};" \
                 : "+f"((acc)[0]), "+f"((acc)[1]), "+f"((acc)[2]), "+f"((acc)[3]) \
                 : "r"((a)[0]), "r"((a)[1]), "r"((a)[2]), "r"((a)[3]), \
                   "r"((b)[0]), "r"((b)[1]))

__device__ __forceinline__ uint32_t ex2_f16x2(uint32_t x) {
    uint32_t r;
    asm volatile("ex2.approx.f16x2 %0, %1;" : "=r"(r) : "r"(x));
    return r;
}
__device__ __forceinline__ float ex2f(float x) {
    float r;
    asm volatile("ex2.approx.f32 %0, %1;" : "=f"(r) : "f"(x));
    return r;
}

// 128B-wide tile (64 halfs/row), swizzled for conflict-free ldmatrix
__device__ __forceinline__ uint32_t tile_off(int row, int ch) {
    return (uint32_t)(row * 128 + ((ch ^ (row & 7)) << 4));
}

__device__ __forceinline__ void cpa16(uint32_t d, const void* s) {
    asm volatile("cp.async.cg.shared.global [%0], [%1], 16;"
                 :: "r"(d), "l"(s) : "memory");
}

// ---------------------------------------------------------------------------
// Fused fp32 -> fp16 conversion, grid-stride x4 (R10 version, incl. Wo).
// ---------------------------------------------------------------------------
#define CVT_N4 4718592
#define CVT_Q  (CVT_N4 / 4)

__device__ __forceinline__ void cvt_one(
    int i,
    const float* __restrict__ x,  const float* __restrict__ wq,
    const float* __restrict__ wk, const float* __restrict__ wv,
    const float* __restrict__ wo)
{
    const float4* s;
    __half2* d;
    int off;
    if (i < 2097152)      { s = (const float4*)x;  d = (__half2*)g_a16;  off = i; }
    else if (i < 3145728) { s = (const float4*)wq; d = (__half2*)g_wq16; off = i - 2097152; }
    else if (i < 3407872) { s = (const float4*)wk; d = (__half2*)g_wk16; off = i - 3145728; }
    else if (i < 3670016) { s = (const float4*)wv; d = (__half2*)g_wv16; off = i - 3407872; }
    else                  { s = (const float4*)wo; d = (__half2*)g_wo16; off = i - 3670016; }
    float4 v = s[off];
    d[2 * off]     = __floats2half2_rn(v.x, v.y);
    d[2 * off + 1] = __floats2half2_rn(v.z, v.w);
}

__global__ void cvt_all(const float* __restrict__ x,  const float* __restrict__ wq,
                        const float* __restrict__ wk, const float* __restrict__ wv,
                        const float* __restrict__ wo)
{
    int j = blockIdx.x * 256 + threadIdx.x;
    if (j >= CVT_Q) return;
    cvt_one(j,             x, wq, wk, wv, wo);
    cvt_one(j + CVT_Q,     x, wq, wk, wv, wo);
    cvt_one(j + 2 * CVT_Q, x, wq, wk, wv, wo);
    cvt_one(j + 3 * CVT_Q, x, wq, wk, wv, wo);
}

// ---------------------------------------------------------------------------
// fp16 GEMM (R10 config): C[128x128 tile] = A[M,K] * W[N,K]^T
// 256 threads / 8 warps (2m x 4n), warp tile 64x32, BK=64, 3-stage cp.async.
// __launch_bounds__(256,2): <=128 regs -> 2 CTAs/SM for cross-CTA overlap.
// FUSED=1: QKV fused (bx 0-15 Q+rope, 16-19 K+rope, 20-23 V), fp16 out.
// FUSED=0: output projection, fp32 store.
// ---------------------------------------------------------------------------
#define GEMM_STAGE 32768              // A 16KB + W 16KB
#define GEMM_SMEM  (3 * GEMM_STAGE)   // 98304 -> 2 CTAs = 192KB/SM

template<int FUSED>
__global__ __launch_bounds__(256, 2)
void gemm_f16(float* __restrict__ out_param,
              const float* __restrict__ cosb, const float* __restrict__ sinb)
{
    extern __shared__ __align__(128) char smem[];
    const uint32_t sb = smem_u32(smem);
    const int tid = threadIdx.x, wid = tid >> 5, lane = tid & 31;
    const int m0 = blockIdx.y * 128;
    const int m_base = (wid & 1) * 64;
    const int n_base = (wid >> 1) * 32;

    const __half* __restrict__ A = g_a16;
    const __half* __restrict__ Wp;
    __half* outh = nullptr;
    int NH_sel = 0, n_local0 = 0;
    bool rope = false;
    if (FUSED) {
        int bx = blockIdx.x;
        if (bx < 16)      { Wp = g_wq16; outh = g_q16; NH_sel = NHQ;  rope = true;  n_local0 = bx * 128; }
        else if (bx < 20) { Wp = g_wk16; outh = g_k16; NH_sel = NHKV; rope = true;  n_local0 = (bx - 16) * 128; }
        else              { Wp = g_wv16; outh = g_v16; NH_sel = NHKV; rope = false; n_local0 = (bx - 20) * 128; }
    } else {
        Wp = g_wo16; n_local0 = blockIdx.x * 128;
    }

    float acc[4][4][4];
#pragma unroll
    for (int mi = 0; mi < 4; mi++)
#pragma unroll
        for (int ni = 0; ni < 4; ni++)
#pragma unroll
            for (int q = 0; q < 4; q++) acc[mi][ni][q] = 0.f;

    auto load_stage = [&](int stage, int k0) {
        uint32_t sbase = sb + stage * GEMM_STAGE;
#pragma unroll
        for (int s = 0; s < 8; s++) {
            int idx = s * 256 + tid;           // 0..2047
            int t   = idx >> 10;               // 0: A, 1: W
            int rem = idx & 1023;
            int row = rem >> 3, ch = rem & 7;
            const __half* g = (t == 0)
                ? A  + (size_t)(m0 + row) * KD + k0 + ch * 8
                : Wp + (size_t)(n_local0 + row) * KD + k0 + ch * 8;
            cpa16(sbase + t * 16384 + tile_off(row, ch), g);
        }
        asm volatile("cp.async.commit_group;" ::: "memory");
    };

    load_stage(0, 0);
    load_stage(1, 64);

    const int l15 = lane & 15, lh = lane >> 4;
    const int bmat = lane >> 3, br = lane & 7;

    for (int c = 0; c < 32; c++) {
        if (c < 31) asm volatile("cp.async.wait_group 1;" ::: "memory");
        else        asm volatile("cp.async.wait_group 0;" ::: "memory");
        __syncthreads();
        if (c + 2 < 32) {
            int st = (c + 2) % 3;
            load_stage(st, (c + 2) * 64);
        }

        uint32_t stg = sb + (c % 3) * GEMM_STAGE;
        uint32_t tA = stg, tW = stg + 16384;

#pragma unroll
        for (int ks = 0; ks < 4; ks++) {
            uint32_t af[4][4], bf[4][2];
#pragma unroll
            for (int mi = 0; mi < 4; mi++) {
                int row = m_base + mi * 16 + l15;
                LDM4(af[mi][0], af[mi][1], af[mi][2], af[mi][3],
                     tA + tile_off(row, 2 * ks + lh));
            }
#pragma unroll
            for (int ng = 0; ng < 2; ng++) {
                int row = n_base + ng * 16 + ((bmat & 2) << 2) + br;
                uint32_t r0, r1, r2, r3;
                LDM4(r0, r1, r2, r3, tW + tile_off(row, 2 * ks + (bmat & 1)));
                bf[ng * 2][0] = r0;     bf[ng * 2][1] = r1;
                bf[ng * 2 + 1][0] = r2; bf[ng * 2 + 1][1] = r3;
            }
#pragma unroll
            for (int mi = 0; mi < 4; mi++)
#pragma unroll
                for (int ni = 0; ni < 4; ni++)
                    MMA16816(acc[mi][ni], af[mi], bf[ni]);
        }
    }

    const int tr = lane >> 2, tc = lane & 3;
#pragma unroll
    for (int mi = 0; mi < 4; mi++) {
#pragma unroll
        for (int ni = 0; ni < 4; ni++) {
            int nloc = n_local0 + n_base + ni * 8 + tc * 2;
#pragma unroll
            for (int half = 0; half < 2; half++) {
                int m = m0 + m_base + mi * 16 + tr + half * 8;
                float e = acc[mi][ni][half * 2];
                float o = acc[mi][ni][half * 2 + 1];
                if (!FUSED) {
                    *(float2*)(out_param + (size_t)m * 2048 + nloc) = make_float2(e, o);
                } else {
                    int bb = m >> 11, s = m & 2047;
                    float oe = e, oo = o;
                    if (rope) {
                        int f = (nloc & (HDIM - 1)) >> 1;
                        float cs = cosb[s * 64 + f];
                        float sn = sinb[s * 64 + f];
                        oe = e * cs - o * sn;
                        oo = e * sn + o * cs;
                    }
                    int h = nloc >> 7, d = nloc & (HDIM - 1);
                    *(__half2*)(outh + (((size_t)bb * NH_sel + h) * SS + s) * HDIM + d) =
                        __floats2half2_rn(oe, oo);
                }
            }
        }
    }
}

// ---------------------------------------------------------------------------
// Tensor-core flash attention (R10 online-max) + diagonal-tile MMA skipping.
// BQ=128, BK=128, HD=128. 8 warps, warp = 16 q-rows. Causal, GQA.
// ---------------------------------------------------------------------------
#define FLASH_SMEM 163840
#define C_EXP 0.12753102f    // (1/sqrt(128)) * log2(e)

__global__ __launch_bounds__(256, 1)
void flash16()
{
    extern __shared__ __align__(128) char fsm[];
    const uint32_t sb = smem_u32(fsm);
    const uint32_t sQ = sb;

    const int tid = threadIdx.x, wid = tid >> 5, lane = tid & 31;
    const int l15 = lane & 15, lh = lane >> 4;
    const int bmat = lane >> 3, br = lane & 7;
    const int tr = lane >> 2, tc = lane & 3;
    const int mrow = wid * 16;

    const int qti = (int)gridDim.x - 1 - (int)blockIdx.x;   // big tiles first
    const int h = blockIdx.y, b = blockIdx.z;
    const int q0 = qti * 128;
    const int kvh = h >> 2;

    const __half* Qg = g_q16 + (((size_t)b * NHQ + h) * SS + q0) * HDIM;
    const __half* Kg = g_k16 + (((size_t)b * NHKV + kvh) * SS) * HDIM;
    const __half* Vg = g_v16 + (((size_t)b * NHKV + kvh) * SS) * HDIM;

#pragma unroll
    for (int i = 0; i < 8; i++) {
        int idx = i * 256 + tid;
        int row = idx >> 4, c = idx & 15;
        cpa16(sQ + (c >> 3) * 16384 + tile_off(row, c & 7),
              Qg + (size_t)row * HDIM + c * 8);
    }

    auto load_kv = [&](int st, int t) {
        uint32_t base = sb + 32768 + st * 65536;
        int k0 = t * 128;
#pragma unroll
        for (int i = 0; i < 16; i++) {
            int idx = i * 256 + tid;
            int kv  = idx >> 11;
            int rem = idx & 2047;
            int row = rem >> 4, c = rem & 15;
            uint32_t off = (c >> 3) * 16384 + tile_off(row, c & 7);
            const __half* g = (kv == 0)
                ? Kg + (size_t)(k0 + row) * HDIM + c * 8
                : Vg + (size_t)(k0 + row) * HDIM + c * 8;
            cpa16(base + kv * 32768 + off, g);
        }
        asm volatile("cp.async.commit_group;" ::: "memory");
    };

    load_kv(0, 0);

    float m0v = -1e30f, m1v = -1e30f, l0 = 0.f, l1 = 0.f;
    float y[16][4];
#pragma unroll
    for (int i = 0; i < 16; i++)
#pragma unroll
        for (int q = 0; q < 4; q++) y[i][q] = 0.f;

    const int nt = qti + 1;
    for (int t = 0; t < nt; t++) {
        if (t + 1 < nt) {
            load_kv((t + 1) & 1, t + 1);
            asm volatile("cp.async.wait_group 1;" ::: "memory");
        } else {
            asm volatile("cp.async.wait_group 0;" ::: "memory");
        }
        __syncthreads();

        uint32_t stg = sb + 32768 + (t & 1) * 65536;
        uint32_t sK = stg, sV = stg + 32768;
        const int k0 = t * 128;
        const bool diag = (t == nt - 1);

        float S[16][4];
#pragma unroll
        for (int ni = 0; ni < 16; ni++)
#pragma unroll
            for (int q = 0; q < 4; q++) S[ni][q] = 0.f;

#pragma unroll
        for (int kc = 0; kc < 8; kc++) {
            uint32_t a[4];
            LDM4(a[0], a[1], a[2], a[3],
                 sQ + (kc >> 2) * 16384 + tile_off(mrow + l15, 2 * (kc & 3) + lh));
#pragma unroll
            for (int ng = 0; ng < 8; ng++) {
                // diagonal tile: warp wid needs only col groups ng <= wid
                if (diag && ng > wid) continue;
                uint32_t r0, r1, r2, r3;
                LDM4(r0, r1, r2, r3,
                     sK + (kc >> 2) * 16384 +
                     tile_off(ng * 16 + ((bmat & 2) << 2) + br, 2 * (kc & 3) + (bmat & 1)));
                uint32_t b0[2] = { r0, r1 }, b1[2] = { r2, r3 };
                MMA16816(S[ng * 2], a, b0);
                MMA16816(S[ng * 2 + 1], a, b1);
            }
        }

        if (diag) {
            int row0 = q0 + mrow + tr, row1 = row0 + 8;
#pragma unroll
            for (int ni = 0; ni < 16; ni++) {
                int col = k0 + ni * 8 + 2 * tc;
                if (col > row0)     S[ni][0] = -1e30f;
                if (col + 1 > row0) S[ni][1] = -1e30f;
                if (col > row1)     S[ni][2] = -1e30f;
                if (col + 1 > row1) S[ni][3] = -1e30f;
            }
        }

        float mx0 = -1e30f, mx1 = -1e30f;
#pragma unroll
        for (int ni = 0; ni < 16; ni++) {
            mx0 = fmaxf(mx0, fmaxf(S[ni][0], S[ni][1]));
            mx1 = fmaxf(mx1, fmaxf(S[ni][2], S[ni][3]));
        }
        mx0 = fmaxf(mx0, __shfl_xor_sync(0xffffffffu, mx0, 1));
        mx0 = fmaxf(mx0, __shfl_xor_sync(0xffffffffu, mx0, 2));
        mx1 = fmaxf(mx1, __shfl_xor_sync(0xffffffffu, mx1, 1));
        mx1 = fmaxf(mx1, __shfl_xor_sync(0xffffffffu, mx1, 2));

        float mn0 = fmaxf(m0v, mx0), mn1 = fmaxf(m1v, mx1);
        float f0 = ex2f((m0v - mn0) * C_EXP);
        float f1 = ex2f((m1v - mn1) * C_EXP);
        m0v = mn0; m1v = mn1;

        uint32_t P[16][2];
        float s0 = 0.f, s1 = 0.f;
#pragma unroll
        for (int ni = 0; ni < 16; ni++) {
            __half2 h0 = __floats2half2_rn((S[ni][0] - mn0) * C_EXP,
                                           (S[ni][1] - mn0) * C_EXP);
            __half2 h1 = __floats2half2_rn((S[ni][2] - mn1) * C_EXP,
                                           (S[ni][3] - mn1) * C_EXP);
            uint32_t p0 = ex2_f16x2(*(uint32_t*)&h0);
            uint32_t p1 = ex2_f16x2(*(uint32_t*)&h1);
            P[ni][0] = p0; P[ni][1] = p1;
            float2 q0f = __half22float2(*(__half2*)&p0);
            float2 q1f = __half22float2(*(__half2*)&p1);
            s0 += q0f.x + q0f.y;
            s1 += q1f.x + q1f.y;
        }
        s0 += __shfl_xor_sync(0xffffffffu, s0, 1);
        s0 += __shfl_xor_sync(0xffffffffu, s0, 2);
        s1 += __shfl_xor_sync(0xffffffffu, s1, 1);
        s1 += __shfl_xor_sync(0xffffffffu, s1, 2);
        l0 = l0 * f0 + s0;
        l1 = l1 * f1 + s1;

#pragma unroll
        for (int i = 0; i < 16; i++) {
            y[i][0] *= f0; y[i][1] *= f0;
            y[i][2] *= f1; y[i][3] *= f1;
        }

#pragma unroll
        for (int kc2 = 0; kc2 < 8; kc2++) {
            // diagonal tile: P rows in group kc2 > wid are exactly zero
            if (diag && kc2 > wid) continue;
            uint32_t a[4] = { P[2 * kc2][0], P[2 * kc2][1],
                              P[2 * kc2 + 1][0], P[2 * kc2 + 1][1] };
#pragma unroll
            for (int dj = 0; dj < 8; dj++) {
                uint32_t r0, r1, r2, r3;
                LDM4T(r0, r1, r2, r3,
                      sV + (dj >> 2) * 16384 +
                      tile_off(kc2 * 16 + l15, ((dj & 3) << 1) + lh));
                uint32_t b0[2] = { r0, r1 }, b1[2] = { r2, r3 };
                MMA16816(y[2 * dj], a, b0);
                MMA16816(y[2 * dj + 1], a, b1);
            }
        }
        __syncthreads();
    }

    float inv0 = 1.f / l0, inv1 = 1.f / l1;
#pragma unroll
    for (int ni = 0; ni < 16; ni++) {
        int col = h * HDIM + ni * 8 + 2 * tc;
        int row0 = q0 + mrow + tr;
        *(__half2*)(g_a16 + ((size_t)b * SS + row0) * HIDD + col) =
            __floats2half2_rn(y[ni][0] * inv0, y[ni][1] * inv0);
        *(__half2*)(g_a16 + ((size_t)b * SS + row0 + 8) * HIDD + col) =
            __floats2half2_rn(y[ni][2] * inv1, y[ni][3] * inv1);
    }
}

// ---------------------------------------------------------------------------
extern "C" void kernel_launch(void* const* d_in, const int* in_sizes, int n_in,
                              void* d_out, int out_size)
{
    const float* x    = (const float*)d_in[0];
    const float* cosb = (const float*)d_in[1];
    const float* sinb = (const float*)d_in[2];
    const float* Wq   = (const float*)d_in[3];
    const float* Wk   = (const float*)d_in[4];
    const float* Wv   = (const float*)d_in[5];
    const float* Wo   = (const float*)d_in[6];
    float* out = (float*)d_out;

    cudaFuncSetAttribute(flash16,
                         cudaFuncAttributeMaxDynamicSharedMemorySize, FLASH_SMEM);
    cudaFuncSetAttribute(gemm_f16<1>,
                         cudaFuncAttributeMaxDynamicSharedMemorySize, GEMM_SMEM);
    cudaFuncSetAttribute(gemm_f16<0>,
                         cudaFuncAttributeMaxDynamicSharedMemorySize, GEMM_SMEM);

    // Fused fp16 conversions (x + all weights)
    cvt_all<<<(CVT_Q + 255) / 256, 256>>>(x, Wq, Wk, Wv, Wo);

    // Fused QKV projection (+RoPE), fp16 outputs  (24 n-tiles x 32 m-tiles)
    gemm_f16<1><<<dim3(24, 32), 256, GEMM_SMEM>>>(nullptr, cosb, sinb);

    // Tensor-core flash attention (online-max, diagonal-skip)
    flash16<<<dim3(SS / 128, NHQ, BB), 256, FLASH_SMEM>>>();

    // Output projection (fp32 out)  (16 n-tiles x 32 m-tiles)
    gemm_f16<0><<<dim3(16, 32), 256, GEMM_SMEM>>>(out, nullptr, nullptr);
}

// round 15
// speedup vs baseline: 1.7451x; 1.7451x over previous
#include <cuda_runtime.h>
#include <cuda_fp16.h>
#include <math.h>
#include <stdint.h>

// Problem constants
#define BB    2
#define SS    2048
#define HIDD  2048
#define NHQ   16
#define NHKV  4
#define HDIM  128
#define KD    2048
#define MTOT  (BB*SS)     // 4096

// ---------------------------------------------------------------------------
// Device-global scratch
// ---------------------------------------------------------------------------
__device__ __half g_q16[(size_t)BB*NHQ *SS*HDIM];   // [B][H][S][HD]
__device__ __half g_k16[(size_t)BB*NHKV*SS*HDIM];
__device__ __half g_v16[(size_t)BB*NHKV*SS*HDIM];

__device__ __half g_a16 [(size_t)MTOT*KD];          // x, then y
__device__ __half g_wq16[(size_t)2048*2048];
__device__ __half g_wk16[(size_t)512*2048];
__device__ __half g_wv16[(size_t)512*2048];
__device__ __half g_wo16[(size_t)2048*2048];

// ---------------------------------------------------------------------------
__device__ __forceinline__ uint32_t smem_u32(const void* p) {
    uint32_t a;
    asm("{ .reg .u64 t; cvta.to.shared.u64 t, %1; cvt.u32.u64 %0, t; }"
        : "=r"(a) : "l"(p));
    return a;
}

#define LDM4(r0, r1, r2, r3, addr) \
    asm volatile("ldmatrix.sync.aligned.m8n8.x4.shared.b16 {%0,%1,%2,%3}, [%4];" \
                 : "=r"(r0), "=r"(r1), "=r"(r2), "=r"(r3) : "r"(addr))

#define LDM4T(r0, r1, r2, r3, addr) \
    asm volatile("ldmatrix.sync.aligned.m8n8.x4.trans.shared.b16 {%0,%1,%2,%3}, [%4];" \
                 : "=r"(r0), "=r"(r1), "=r"(r2), "=r"(r3) : "r"(addr))

#define MMA16816(acc, a, b) \
    asm volatile("mma.sync.aligned.m16n8k16.row.col.f32.f16.f16.f32 " \
                 "{%0,%1,%2,%3},{%4,%5,%6,%7},{%8,%9},{%0,%1,%2,%3};" \
                 : "+f"((acc)[0]), "+f"((acc)[1]), "+f"((acc)[2]), "+f"((acc)[3]) \
                 : "r"((a)[0]), "r"((a)[1]), "r"((a)[2]), "r"((a)[3]), \
                   "r"((b)[0]), "r"((b)[1]))

__device__ __forceinline__ uint32_t ex2_f16x2(uint32_t x) {
    uint32_t r;
    asm volatile("ex2.approx.f16x2 %0, %1;" : "=r"(r) : "r"(x));
    return r;
}
__device__ __forceinline__ float ex2f(float x) {
    float r;
    asm volatile("ex2.approx.f32 %0, %1;" : "=f"(r) : "f"(x));
    return r;
}

// 128B-wide tile (64 halfs/row), swizzled for conflict-free ldmatrix
__device__ __forceinline__ uint32_t tile_off(int row, int ch) {
    return (uint32_t)(row * 128 + ((ch ^ (row & 7)) << 4));
}

__device__ __forceinline__ void cpa16(uint32_t d, const void* s) {
    asm volatile("cp.async.cg.shared.global [%0], [%1], 16;"
                 :: "r"(d), "l"(s) : "memory");
}

// ---------------------------------------------------------------------------
// Fused fp32 -> fp16 conversion, grid-stride x4 (incl. Wo).
// ---------------------------------------------------------------------------
#define CVT_N4 4718592
#define CVT_Q  (CVT_N4 / 4)

__device__ __forceinline__ void cvt_one(
    int i,
    const float* __restrict__ x,  const float* __restrict__ wq,
    const float* __restrict__ wk, const float* __restrict__ wv,
    const float* __restrict__ wo)
{
    const float4* s;
    __half2* d;
    int off;
    if (i < 2097152)      { s = (const float4*)x;  d = (__half2*)g_a16;  off = i; }
    else if (i < 3145728) { s = (const float4*)wq; d = (__half2*)g_wq16; off = i - 2097152; }
    else if (i < 3407872) { s = (const float4*)wk; d = (__half2*)g_wk16; off = i - 3145728; }
    else if (i < 3670016) { s = (const float4*)wv; d = (__half2*)g_wv16; off = i - 3407872; }
    else                  { s = (const float4*)wo; d = (__half2*)g_wo16; off = i - 3670016; }
    float4 v = s[off];
    d[2 * off]     = __floats2half2_rn(v.x, v.y);
    d[2 * off + 1] = __floats2half2_rn(v.z, v.w);
}

__global__ void cvt_all(const float* __restrict__ x,  const float* __restrict__ wq,
                        const float* __restrict__ wk, const float* __restrict__ wv,
                        const float* __restrict__ wo)
{
    int j = blockIdx.x * 256 + threadIdx.x;
    if (j >= CVT_Q) return;
    cvt_one(j,             x, wq, wk, wv, wo);
    cvt_one(j + CVT_Q,     x, wq, wk, wv, wo);
    cvt_one(j + 2 * CVT_Q, x, wq, wk, wv, wo);
    cvt_one(j + 3 * CVT_Q, x, wq, wk, wv, wo);
}

// ---------------------------------------------------------------------------
// fp16 GEMM (R10 config): C[128x128 tile] = A[M,K] * W[N,K]^T
// 256 threads / 8 warps (2m x 4n), warp tile 64x32, BK=64, 3-stage cp.async.
// __launch_bounds__(256,2): <=128 regs -> 2 CTAs/SM for cross-CTA overlap.
// FUSED=1: QKV fused (bx 0-15 Q+rope, 16-19 K+rope, 20-23 V), fp16 out.
// FUSED=0: output projection, fp32 store.
// ---------------------------------------------------------------------------
#define GEMM_STAGE 32768              // A 16KB + W 16KB
#define GEMM_SMEM  (3 * GEMM_STAGE)   // 98304 -> 2 CTAs = 192KB/SM

template<int FUSED>
__global__ __launch_bounds__(256, 2)
void gemm_f16(float* __restrict__ out_param,
              const float* __restrict__ cosb, const float* __restrict__ sinb)
{
    extern __shared__ __align__(128) char smem[];
    const uint32_t sb = smem_u32(smem);
    const int tid = threadIdx.x, wid = tid >> 5, lane = tid & 31;
    const int m0 = blockIdx.y * 128;
    const int m_base = (wid & 1) * 64;
    const int n_base = (wid >> 1) * 32;

    const __half* __restrict__ A = g_a16;
    const __half* __restrict__ Wp;
    __half* outh = nullptr;
    int NH_sel = 0, n_local0 = 0;
    bool rope = false;
    if (FUSED) {
        int bx = blockIdx.x;
        if (bx < 16)      { Wp = g_wq16; outh = g_q16; NH_sel = NHQ;  rope = true;  n_local0 = bx * 128; }
        else if (bx < 20) { Wp = g_wk16; outh = g_k16; NH_sel = NHKV; rope = true;  n_local0 = (bx - 16) * 128; }
        else              { Wp = g_wv16; outh = g_v16; NH_sel = NHKV; rope = false; n_local0 = (bx - 20) * 128; }
    } else {
        Wp = g_wo16; n_local0 = blockIdx.x * 128;
    }

    float acc[4][4][4];
#pragma unroll
    for (int mi = 0; mi < 4; mi++)
#pragma unroll
        for (int ni = 0; ni < 4; ni++)
#pragma unroll
            for (int q = 0; q < 4; q++) acc[mi][ni][q] = 0.f;

    auto load_stage = [&](int stage, int k0) {
        uint32_t sbase = sb + stage * GEMM_STAGE;
#pragma unroll
        for (int s = 0; s < 8; s++) {
            int idx = s * 256 + tid;           // 0..2047
            int t   = idx >> 10;               // 0: A, 1: W
            int rem = idx & 1023;
            int row = rem >> 3, ch = rem & 7;
            const __half* g = (t == 0)
                ? A  + (size_t)(m0 + row) * KD + k0 + ch * 8
                : Wp + (size_t)(n_local0 + row) * KD + k0 + ch * 8;
            cpa16(sbase + t * 16384 + tile_off(row, ch), g);
        }
        asm volatile("cp.async.commit_group;" ::: "memory");
    };

    load_stage(0, 0);
    load_stage(1, 64);

    const int l15 = lane & 15, lh = lane >> 4;
    const int bmat = lane >> 3, br = lane & 7;

    for (int c = 0; c < 32; c++) {
        if (c < 31) asm volatile("cp.async.wait_group 1;" ::: "memory");
        else        asm volatile("cp.async.wait_group 0;" ::: "memory");
        __syncthreads();
        if (c + 2 < 32) {
            int st = (c + 2) % 3;
            load_stage(st, (c + 2) * 64);
        }

        uint32_t stg = sb + (c % 3) * GEMM_STAGE;
        uint32_t tA = stg, tW = stg + 16384;

#pragma unroll
        for (int ks = 0; ks < 4; ks++) {
            uint32_t af[4][4], bf[4][2];
#pragma unroll
            for (int mi = 0; mi < 4; mi++) {
                int row = m_base + mi * 16 + l15;
                LDM4(af[mi][0], af[mi][1], af[mi][2], af[mi][3],
                     tA + tile_off(row, 2 * ks + lh));
            }
#pragma unroll
            for (int ng = 0; ng < 2; ng++) {
                int row = n_base + ng * 16 + ((bmat & 2) << 2) + br;
                uint32_t r0, r1, r2, r3;
                LDM4(r0, r1, r2, r3, tW + tile_off(row, 2 * ks + (bmat & 1)));
                bf[ng * 2][0] = r0;     bf[ng * 2][1] = r1;
                bf[ng * 2 + 1][0] = r2; bf[ng * 2 + 1][1] = r3;
            }
#pragma unroll
            for (int mi = 0; mi < 4; mi++)
#pragma unroll
                for (int ni = 0; ni < 4; ni++)
                    MMA16816(acc[mi][ni], af[mi], bf[ni]);
        }
    }

    const int tr = lane >> 2, tc = lane & 3;
#pragma unroll
    for (int mi = 0; mi < 4; mi++) {
#pragma unroll
        for (int ni = 0; ni < 4; ni++) {
            int nloc = n_local0 + n_base + ni * 8 + tc * 2;
#pragma unroll
            for (int half = 0; half < 2; half++) {
                int m = m0 + m_base + mi * 16 + tr + half * 8;
                float e = acc[mi][ni][half * 2];
                float o = acc[mi][ni][half * 2 + 1];
                if (!FUSED) {
                    *(float2*)(out_param + (size_t)m * 2048 + nloc) = make_float2(e, o);
                } else {
                    int bb = m >> 11, s = m & 2047;
                    float oe = e, oo = o;
                    if (rope) {
                        int f = (nloc & (HDIM - 1)) >> 1;
                        float cs = cosb[s * 64 + f];
                        float sn = sinb[s * 64 + f];
                        oe = e * cs - o * sn;
                        oo = e * sn + o * cs;
                    }
                    int h = nloc >> 7, d = nloc & (HDIM - 1);
                    *(__half2*)(outh + (((size_t)bb * NH_sel + h) * SS + s) * HDIM + d) =
                        __floats2half2_rn(oe, oo);
                }
            }
        }
    }
}

// ---------------------------------------------------------------------------
// Tensor-core flash attention (online-max) + diagonal-tile MMA skipping.
// BQ=128, BK=128, HD=128. 8 warps, warp = 16 q-rows. Causal, GQA.
// ---------------------------------------------------------------------------
#define FLASH_SMEM 163840
#define C_EXP 0.12753102f    // (1/sqrt(128)) * log2(e)

__global__ __launch_bounds__(256, 1)
void flash16()
{
    extern __shared__ __align__(128) char fsm[];
    const uint32_t sb = smem_u32(fsm);
    const uint32_t sQ = sb;

    const int tid = threadIdx.x, wid = tid >> 5, lane = tid & 31;
    const int l15 = lane & 15, lh = lane >> 4;
    const int bmat = lane >> 3, br = lane & 7;
    const int tr = lane >> 2, tc = lane & 3;
    const int mrow = wid * 16;

    const int qti = (int)gridDim.x - 1 - (int)blockIdx.x;   // big tiles first
    const int h = blockIdx.y, b = blockIdx.z;
    const int q0 = qti * 128;
    const int kvh = h >> 2;

    const __half* Qg = g_q16 + (((size_t)b * NHQ + h) * SS + q0) * HDIM;
    const __half* Kg = g_k16 + (((size_t)b * NHKV + kvh) * SS) * HDIM;
    const __half* Vg = g_v16 + (((size_t)b * NHKV + kvh) * SS) * HDIM;

#pragma unroll
    for (int i = 0; i < 8; i++) {
        int idx = i * 256 + tid;
        int row = idx >> 4, c = idx & 15;
        cpa16(sQ + (c >> 3) * 16384 + tile_off(row, c & 7),
              Qg + (size_t)row * HDIM + c * 8);
    }

    auto load_kv = [&](int st, int t) {
        uint32_t base = sb + 32768 + st * 65536;
        int k0 = t * 128;
#pragma unroll
        for (int i = 0; i < 16; i++) {
            int idx = i * 256 + tid;
            int kv  = idx >> 11;
            int rem = idx & 2047;
            int row = rem >> 4, c = rem & 15;
            uint32_t off = (c >> 3) * 16384 + tile_off(row, c & 7);
            const __half* g = (kv == 0)
                ? Kg + (size_t)(k0 + row) * HDIM + c * 8
                : Vg + (size_t)(k0 + row) * HDIM + c * 8;
            cpa16(base + kv * 32768 + off, g);
        }
        asm volatile("cp.async.commit_group;" ::: "memory");
    };

    load_kv(0, 0);

    float m0v = -1e30f, m1v = -1e30f, l0 = 0.f, l1 = 0.f;
    float y[16][4];
#pragma unroll
    for (int i = 0; i < 16; i++)
#pragma unroll
        for (int q = 0; q < 4; q++) y[i][q] = 0.f;

    const int nt = qti + 1;
    for (int t = 0; t < nt; t++) {
        if (t + 1 < nt) {
            load_kv((t + 1) & 1, t + 1);
            asm volatile("cp.async.wait_group 1;" ::: "memory");
        } else {
            asm volatile("cp.async.wait_group 0;" ::: "memory");
        }
        __syncthreads();

        uint32_t stg = sb + 32768 + (t & 1) * 65536;
        uint32_t sK = stg, sV = stg + 32768;
        const int k0 = t * 128;
        const bool diag = (t == nt - 1);

        float S[16][4];
#pragma unroll
        for (int ni = 0; ni < 16; ni++)
#pragma unroll
            for (int q = 0; q < 4; q++) S[ni][q] = 0.f;

#pragma unroll
        for (int kc = 0; kc < 8; kc++) {
            uint32_t a[4];
            LDM4(a[0], a[1], a[2], a[3],
                 sQ + (kc >> 2) * 16384 + tile_off(mrow + l15, 2 * (kc & 3) + lh));
#pragma unroll
            for (int ng = 0; ng < 8; ng++) {
                // diagonal tile: warp wid needs only col groups ng <= wid
                if (diag && ng > wid) continue;
                uint32_t r0, r1, r2, r3;
                LDM4(r0, r1, r2, r3,
                     sK + (kc >> 2) * 16384 +
                     tile_off(ng * 16 + ((bmat & 2) << 2) + br, 2 * (kc & 3) + (bmat & 1)));
                uint32_t b0[2] = { r0, r1 }, b1[2] = { r2, r3 };
                MMA16816(S[ng * 2], a, b0);
                MMA16816(S[ng * 2 + 1], a, b1);
            }
        }

        if (diag) {
            int row0 = q0 + mrow + tr, row1 = row0 + 8;
#pragma unroll
            for (int ni = 0; ni < 16; ni++) {
                int col = k0 + ni * 8 + 2 * tc;
                if (col > row0)     S[ni][0] = -1e30f;
                if (col + 1 > row0) S[ni][1] = -1e30f;
                if (col > row1)     S[ni][2] = -1e30f;
                if (col + 1 > row1) S[ni][3] = -1e30f;
            }
        }

        float mx0 = -1e30f, mx1 = -1e30f;
#pragma unroll
        for (int ni = 0; ni < 16; ni++) {
            mx0 = fmaxf(mx0, fmaxf(S[ni][0], S[ni][1]));
            mx1 = fmaxf(mx1, fmaxf(S[ni][2], S[ni][3]));
        }
        mx0 = fmaxf(mx0, __shfl_xor_sync(0xffffffffu, mx0, 1));
        mx0 = fmaxf(mx0, __shfl_xor_sync(0xffffffffu, mx0, 2));
        mx1 = fmaxf(mx1, __shfl_xor_sync(0xffffffffu, mx1, 1));
        mx1 = fmaxf(mx1, __shfl_xor_sync(0xffffffffu, mx1, 2));

        float mn0 = fmaxf(m0v, mx0), mn1 = fmaxf(m1v, mx1);
        float f0 = ex2f((m0v - mn0) * C_EXP);
        float f1 = ex2f((m1v - mn1) * C_EXP);
        m0v = mn0; m1v = mn1;

        uint32_t P[16][2];
        float s0 = 0.f, s1 = 0.f;
#pragma unroll
        for (int ni = 0; ni < 16; ni++) {
            __half2 h0 = __floats2half2_rn((S[ni][0] - mn0) * C_EXP,
                                           (S[ni][1] - mn0) * C_EXP);
            __half2 h1 = __floats2half2_rn((S[ni][2] - mn1) * C_EXP,
                                           (S[ni][3] - mn1) * C_EXP);
            uint32_t p0 = ex2_f16x2(*(uint32_t*)&h0);
            uint32_t p1 = ex2_f16x2(*(uint32_t*)&h1);
            P[ni][0] = p0; P[ni][1] = p1;
            float2 q0f = __half22float2(*(__half2*)&p0);
            float2 q1f = __half22float2(*(__half2*)&p1);
            s0 += q0f.x + q0f.y;
            s1 += q1f.x + q1f.y;
        }
        s0 += __shfl_xor_sync(0xffffffffu, s0, 1);
        s0 += __shfl_xor_sync(0xffffffffu, s0, 2);
        s1 += __shfl_xor_sync(0xffffffffu, s1, 1);
        s1 += __shfl_xor_sync(0xffffffffu, s1, 2);
        l0 = l0 * f0 + s0;
        l1 = l1 * f1 + s1;

#pragma unroll
        for (int i = 0; i < 16; i++) {
            y[i][0] *= f0; y[i][1] *= f0;
            y[i][2] *= f1; y[i][3] *= f1;
        }

#pragma unroll
        for (int kc2 = 0; kc2 < 8; kc2++) {
            // diagonal tile: P rows in group kc2 > wid are exactly zero
            if (diag && kc2 > wid) continue;
            uint32_t a[4] = { P[2 * kc2][0], P[2 * kc2][1],
                              P[2 * kc2 + 1][0], P[2 * kc2 + 1][1] };
#pragma unroll
            for (int dj = 0; dj < 8; dj++) {
                uint32_t r0, r1, r2, r3;
                LDM4T(r0, r1, r2, r3,
                      sV + (dj >> 2) * 16384 +
                      tile_off(kc2 * 16 + l15, ((dj & 3) << 1) + lh));
                uint32_t b0[2] = { r0, r1 }, b1[2] = { r2, r3 };
                MMA16816(y[2 * dj], a, b0);
                MMA16816(y[2 * dj + 1], a, b1);
            }
        }
        __syncthreads();
    }

    float inv0 = 1.f / l0, inv1 = 1.f / l1;
#pragma unroll
    for (int ni = 0; ni < 16; ni++) {
        int col = h * HDIM + ni * 8 + 2 * tc;
        int row0 = q0 + mrow + tr;
        *(__half2*)(g_a16 + ((size_t)b * SS + row0) * HIDD + col) =
            __floats2half2_rn(y[ni][0] * inv0, y[ni][1] * inv0);
        *(__half2*)(g_a16 + ((size_t)b * SS + row0 + 8) * HIDD + col) =
            __floats2half2_rn(y[ni][2] * inv1, y[ni][3] * inv1);
    }
}

// ---------------------------------------------------------------------------
extern "C" void kernel_launch(void* const* d_in, const int* in_sizes, int n_in,
                              void* d_out, int out_size)
{
    const float* x    = (const float*)d_in[0];
    const float* cosb = (const float*)d_in[1];
    const float* sinb = (const float*)d_in[2];
    const float* Wq   = (const float*)d_in[3];
    const float* Wk   = (const float*)d_in[4];
    const float* Wv   = (const float*)d_in[5];
    const float* Wo   = (const float*)d_in[6];
    float* out = (float*)d_out;

    cudaFuncSetAttribute(flash16,
                         cudaFuncAttributeMaxDynamicSharedMemorySize, FLASH_SMEM);
    cudaFuncSetAttribute(gemm_f16<1>,
                         cudaFuncAttributeMaxDynamicSharedMemorySize, GEMM_SMEM);
    cudaFuncSetAttribute(gemm_f16<0>,
                         cudaFuncAttributeMaxDynamicSharedMemorySize, GEMM_SMEM);

    // Fused fp16 conversions (x + all weights)
    cvt_all<<<(CVT_Q + 255) / 256, 256>>>(x, Wq, Wk, Wv, Wo);

    // Fused QKV projection (+RoPE), fp16 outputs  (24 n-tiles x 32 m-tiles)
    gemm_f16<1><<<dim3(24, 32), 256, GEMM_SMEM>>>(nullptr, cosb, sinb);

    // Tensor-core flash attention (online-max, diagonal-skip)
    flash16<<<dim3(SS / 128, NHQ, BB), 256, FLASH_SMEM>>>();

    // Output projection (fp32 out)  (16 n-tiles x 32 m-tiles)
    gemm_f16<0><<<dim3(16, 32), 256, GEMM_SMEM>>>(out, nullptr, nullptr);
}

// round 16
// speedup vs baseline: 1.8358x; 1.0520x over previous
#include <cuda_runtime.h>
#include <cuda_fp16.h>
#include <math.h>
#include <stdint.h>

// Problem constants
#define BB    2
#define SS    2048
#define HIDD  2048
#define NHQ   16
#define NHKV  4
#define HDIM  128
#define KD    2048
#define MTOT  (BB*SS)     // 4096

// ---------------------------------------------------------------------------
// Device-global scratch
// ---------------------------------------------------------------------------
__device__ __half g_q16[(size_t)BB*NHQ *SS*HDIM];   // [B][H][S][HD]
__device__ __half g_k16[(size_t)BB*NHKV*SS*HDIM];
__device__ __half g_v16[(size_t)BB*NHKV*SS*HDIM];

__device__ __half g_a16 [(size_t)MTOT*KD];          // x, then y
__device__ __half g_wq16[(size_t)2048*2048];
__device__ __half g_wk16[(size_t)512*2048];
__device__ __half g_wv16[(size_t)512*2048];
__device__ __half g_wo16[(size_t)2048*2048];

// ---------------------------------------------------------------------------
__device__ __forceinline__ uint32_t smem_u32(const void* p) {
    uint32_t a;
    asm("{ .reg .u64 t; cvta.to.shared.u64 t, %1; cvt.u32.u64 %0, t; }"
        : "=r"(a) : "l"(p));
    return a;
}

#define LDM4(r0, r1, r2, r3, addr) \
    asm volatile("ldmatrix.sync.aligned.m8n8.x4.shared.b16 {%0,%1,%2,%3}, [%4];" \
                 : "=r"(r0), "=r"(r1), "=r"(r2), "=r"(r3) : "r"(addr))

#define LDM4T(r0, r1, r2, r3, addr) \
    asm volatile("ldmatrix.sync.aligned.m8n8.x4.trans.shared.b16 {%0,%1,%2,%3}, [%4];" \
                 : "=r"(r0), "=r"(r1), "=r"(r2), "=r"(r3) : "r"(addr))

#define MMA16816(acc, a, b) \
    asm volatile("mma.sync.aligned.m16n8k16.row.col.f32.f16.f16.f32 " \
                 "{%0,%1,%2,%3},{%4,%5,%6,%7},{%8,%9},{%0,%1,%2,%3};" \
                 : "+f"((acc)[0]), "+f"((acc)[1]), "+f"((acc)[2]), "+f"((acc)[3]) \
                 : "r"((a)[0]), "r"((a)[1]), "r"((a)[2]), "r"((a)[3]), \
                   "r"((b)[0]), "r"((b)[1]))

__device__ __forceinline__ uint32_t ex2_f16x2(uint32_t x) {
    uint32_t r;
    asm volatile("ex2.approx.f16x2 %0, %1;" : "=r"(r) : "r"(x));
    return r;
}
__device__ __forceinline__ float ex2f(float x) {
    float r;
    asm volatile("ex2.approx.f32 %0, %1;" : "=f"(r) : "f"(x));
    return r;
}

// 128B-wide tile (64 halfs/row), swizzled for conflict-free ldmatrix
__device__ __forceinline__ uint32_t tile_off(int row, int ch) {
    return (uint32_t)(row * 128 + ((ch ^ (row & 7)) << 4));
}

__device__ __forceinline__ void cpa16(uint32_t d, const void* s) {
    asm volatile("cp.async.cg.shared.global [%0], [%1], 16;"
                 :: "r"(d), "l"(s) : "memory");
}

// ---------------------------------------------------------------------------
// Fused fp32 -> fp16 conversion, grid-stride x4 (incl. Wo).
// ---------------------------------------------------------------------------
#define CVT_N4 4718592
#define CVT_Q  (CVT_N4 / 4)

__device__ __forceinline__ void cvt_one(
    int i,
    const float* __restrict__ x,  const float* __restrict__ wq,
    const float* __restrict__ wk, const float* __restrict__ wv,
    const float* __restrict__ wo)
{
    const float4* s;
    __half2* d;
    int off;
    if (i < 2097152)      { s = (const float4*)x;  d = (__half2*)g_a16;  off = i; }
    else if (i < 3145728) { s = (const float4*)wq; d = (__half2*)g_wq16; off = i - 2097152; }
    else if (i < 3407872) { s = (const float4*)wk; d = (__half2*)g_wk16; off = i - 3145728; }
    else if (i < 3670016) { s = (const float4*)wv; d = (__half2*)g_wv16; off = i - 3407872; }
    else                  { s = (const float4*)wo; d = (__half2*)g_wo16; off = i - 3670016; }
    float4 v = s[off];
    d[2 * off]     = __floats2half2_rn(v.x, v.y);
    d[2 * off + 1] = __floats2half2_rn(v.z, v.w);
}

__global__ void cvt_all(const float* __restrict__ x,  const float* __restrict__ wq,
                        const float* __restrict__ wk, const float* __restrict__ wv,
                        const float* __restrict__ wo)
{
    int j = blockIdx.x * 256 + threadIdx.x;
    if (j >= CVT_Q) return;
    cvt_one(j,             x, wq, wk, wv, wo);
    cvt_one(j + CVT_Q,     x, wq, wk, wv, wo);
    cvt_one(j + 2 * CVT_Q, x, wq, wk, wv, wo);
    cvt_one(j + 3 * CVT_Q, x, wq, wk, wv, wo);
}

// ---------------------------------------------------------------------------
// fp16 GEMM (R10 config): C[128x128 tile] = A[M,K] * W[N,K]^T
// 256 threads / 8 warps (2m x 4n), warp tile 64x32, BK=64, 3-stage cp.async.
// __launch_bounds__(256,2): <=128 regs -> 2 CTAs/SM for cross-CTA overlap.
// ---------------------------------------------------------------------------
#define GEMM_STAGE 32768              // A 16KB + W 16KB
#define GEMM_SMEM  (3 * GEMM_STAGE)   // 98304 -> 2 CTAs = 192KB/SM

template<int FUSED>
__global__ __launch_bounds__(256, 2)
void gemm_f16(float* __restrict__ out_param,
              const float* __restrict__ cosb, const float* __restrict__ sinb)
{
    extern __shared__ __align__(128) char smem[];
    const uint32_t sb = smem_u32(smem);
    const int tid = threadIdx.x, wid = tid >> 5, lane = tid & 31;
    const int m0 = blockIdx.y * 128;
    const int m_base = (wid & 1) * 64;
    const int n_base = (wid >> 1) * 32;

    const __half* __restrict__ A = g_a16;
    const __half* __restrict__ Wp;
    __half* outh = nullptr;
    int NH_sel = 0, n_local0 = 0;
    bool rope = false;
    if (FUSED) {
        int bx = blockIdx.x;
        if (bx < 16)      { Wp = g_wq16; outh = g_q16; NH_sel = NHQ;  rope = true;  n_local0 = bx * 128; }
        else if (bx < 20) { Wp = g_wk16; outh = g_k16; NH_sel = NHKV; rope = true;  n_local0 = (bx - 16) * 128; }
        else              { Wp = g_wv16; outh = g_v16; NH_sel = NHKV; rope = false; n_local0 = (bx - 20) * 128; }
    } else {
        Wp = g_wo16; n_local0 = blockIdx.x * 128;
    }

    float acc[4][4][4];
#pragma unroll
    for (int mi = 0; mi < 4; mi++)
#pragma unroll
        for (int ni = 0; ni < 4; ni++)
#pragma unroll
            for (int q = 0; q < 4; q++) acc[mi][ni][q] = 0.f;

    auto load_stage = [&](int stage, int k0) {
        uint32_t sbase = sb + stage * GEMM_STAGE;
#pragma unroll
        for (int s = 0; s < 8; s++) {
            int idx = s * 256 + tid;           // 0..2047
            int t   = idx >> 10;               // 0: A, 1: W
            int rem = idx & 1023;
            int row = rem >> 3, ch = rem & 7;
            const __half* g = (t == 0)
                ? A  + (size_t)(m0 + row) * KD + k0 + ch * 8
                : Wp + (size_t)(n_local0 + row) * KD + k0 + ch * 8;
            cpa16(sbase + t * 16384 + tile_off(row, ch), g);
        }
        asm volatile("cp.async.commit_group;" ::: "memory");
    };

    load_stage(0, 0);
    load_stage(1, 64);

    const int l15 = lane & 15, lh = lane >> 4;
    const int bmat = lane >> 3, br = lane & 7;

    for (int c = 0; c < 32; c++) {
        if (c < 31) asm volatile("cp.async.wait_group 1;" ::: "memory");
        else        asm volatile("cp.async.wait_group 0;" ::: "memory");
        __syncthreads();
        if (c + 2 < 32) {
            int st = (c + 2) % 3;
            load_stage(st, (c + 2) * 64);
        }

        uint32_t stg = sb + (c % 3) * GEMM_STAGE;
        uint32_t tA = stg, tW = stg + 16384;

#pragma unroll
        for (int ks = 0; ks < 4; ks++) {
            uint32_t af[4][4], bf[4][2];
#pragma unroll
            for (int mi = 0; mi < 4; mi++) {
                int row = m_base + mi * 16 + l15;
                LDM4(af[mi][0], af[mi][1], af[mi][2], af[mi][3],
                     tA + tile_off(row, 2 * ks + lh));
            }
#pragma unroll
            for (int ng = 0; ng < 2; ng++) {
                int row = n_base + ng * 16 + ((bmat & 2) << 2) + br;
                uint32_t r0, r1, r2, r3;
                LDM4(r0, r1, r2, r3, tW + tile_off(row, 2 * ks + (bmat & 1)));
                bf[ng * 2][0] = r0;     bf[ng * 2][1] = r1;
                bf[ng * 2 + 1][0] = r2; bf[ng * 2 + 1][1] = r3;
            }
#pragma unroll
            for (int mi = 0; mi < 4; mi++)
#pragma unroll
                for (int ni = 0; ni < 4; ni++)
                    MMA16816(acc[mi][ni], af[mi], bf[ni]);
        }
    }

    const int tr = lane >> 2, tc = lane & 3;
#pragma unroll
    for (int mi = 0; mi < 4; mi++) {
#pragma unroll
        for (int ni = 0; ni < 4; ni++) {
            int nloc = n_local0 + n_base + ni * 8 + tc * 2;
#pragma unroll
            for (int half = 0; half < 2; half++) {
                int m = m0 + m_base + mi * 16 + tr + half * 8;
                float e = acc[mi][ni][half * 2];
                float o = acc[mi][ni][half * 2 + 1];
                if (!FUSED) {
                    *(float2*)(out_param + (size_t)m * 2048 + nloc) = make_float2(e, o);
                } else {
                    int bb = m >> 11, s = m & 2047;
                    float oe = e, oo = o;
                    if (rope) {
                        int f = (nloc & (HDIM - 1)) >> 1;
                        float cs = cosb[s * 64 + f];
                        float sn = sinb[s * 64 + f];
                        oe = e * cs - o * sn;
                        oo = e * sn + o * cs;
                    }
                    int h = nloc >> 7, d = nloc & (HDIM - 1);
                    *(__half2*)(outh + (((size_t)bb * NH_sel + h) * SS + s) * HDIM + d) =
                        __floats2half2_rn(oe, oo);
                }
            }
        }
    }
}

// ---------------------------------------------------------------------------
// Tensor-core flash attention: R10 mainloop VERBATIM (branch-free full tiles)
// + PEELED diagonal tile with wid-bounded dynamic loops.
// BQ=128, BK=128, HD=128. 8 warps, warp = 16 q-rows. Causal, GQA.
// ---------------------------------------------------------------------------
#define FLASH_SMEM 163840
#define C_EXP 0.12753102f    // (1/sqrt(128)) * log2(e)

__global__ __launch_bounds__(256, 1)
void flash16()
{
    extern __shared__ __align__(128) char fsm[];
    const uint32_t sb = smem_u32(fsm);
    const uint32_t sQ = sb;

    const int tid = threadIdx.x, wid = tid >> 5, lane = tid & 31;
    const int l15 = lane & 15, lh = lane >> 4;
    const int bmat = lane >> 3, br = lane & 7;
    const int tr = lane >> 2, tc = lane & 3;
    const int mrow = wid * 16;

    const int qti = (int)gridDim.x - 1 - (int)blockIdx.x;   // big tiles first
    const int h = blockIdx.y, b = blockIdx.z;
    const int q0 = qti * 128;
    const int kvh = h >> 2;

    const __half* Qg = g_q16 + (((size_t)b * NHQ + h) * SS + q0) * HDIM;
    const __half* Kg = g_k16 + (((size_t)b * NHKV + kvh) * SS) * HDIM;
    const __half* Vg = g_v16 + (((size_t)b * NHKV + kvh) * SS) * HDIM;

#pragma unroll
    for (int i = 0; i < 8; i++) {
        int idx = i * 256 + tid;
        int row = idx >> 4, c = idx & 15;
        cpa16(sQ + (c >> 3) * 16384 + tile_off(row, c & 7),
              Qg + (size_t)row * HDIM + c * 8);
    }

    auto load_kv = [&](int st, int t) {
        uint32_t base = sb + 32768 + st * 65536;
        int k0 = t * 128;
#pragma unroll
        for (int i = 0; i < 16; i++) {
            int idx = i * 256 + tid;
            int kv  = idx >> 11;
            int rem = idx & 2047;
            int row = rem >> 4, c = rem & 15;
            uint32_t off = (c >> 3) * 16384 + tile_off(row, c & 7);
            const __half* g = (kv == 0)
                ? Kg + (size_t)(k0 + row) * HDIM + c * 8
                : Vg + (size_t)(k0 + row) * HDIM + c * 8;
            cpa16(base + kv * 32768 + off, g);
        }
        asm volatile("cp.async.commit_group;" ::: "memory");
    };

    load_kv(0, 0);

    float m0v = -1e30f, m1v = -1e30f, l0 = 0.f, l1 = 0.f;
    float y[16][4];
#pragma unroll
    for (int i = 0; i < 16; i++)
#pragma unroll
        for (int q = 0; q < 4; q++) y[i][q] = 0.f;

    const int nt = qti + 1;

    // ===================== mainloop: full tiles (R10 body, branch-free) ====
    for (int t = 0; t < nt - 1; t++) {
        load_kv((t + 1) & 1, t + 1);
        asm volatile("cp.async.wait_group 1;" ::: "memory");
        __syncthreads();

        uint32_t stg = sb + 32768 + (t & 1) * 65536;
        uint32_t sK = stg, sV = stg + 32768;

        float S[16][4];
#pragma unroll
        for (int ni = 0; ni < 16; ni++)
#pragma unroll
            for (int q = 0; q < 4; q++) S[ni][q] = 0.f;

#pragma unroll
        for (int kc = 0; kc < 8; kc++) {
            uint32_t a[4];
            LDM4(a[0], a[1], a[2], a[3],
                 sQ + (kc >> 2) * 16384 + tile_off(mrow + l15, 2 * (kc & 3) + lh));
#pragma unroll
            for (int ng = 0; ng < 8; ng++) {
                uint32_t r0, r1, r2, r3;
                LDM4(r0, r1, r2, r3,
                     sK + (kc >> 2) * 16384 +
                     tile_off(ng * 16 + ((bmat & 2) << 2) + br, 2 * (kc & 3) + (bmat & 1)));
                uint32_t b0[2] = { r0, r1 }, b1[2] = { r2, r3 };
                MMA16816(S[ng * 2], a, b0);
                MMA16816(S[ng * 2 + 1], a, b1);
            }
        }

        float mx0 = -1e30f, mx1 = -1e30f;
#pragma unroll
        for (int ni = 0; ni < 16; ni++) {
            mx0 = fmaxf(mx0, fmaxf(S[ni][0], S[ni][1]));
            mx1 = fmaxf(mx1, fmaxf(S[ni][2], S[ni][3]));
        }
        mx0 = fmaxf(mx0, __shfl_xor_sync(0xffffffffu, mx0, 1));
        mx0 = fmaxf(mx0, __shfl_xor_sync(0xffffffffu, mx0, 2));
        mx1 = fmaxf(mx1, __shfl_xor_sync(0xffffffffu, mx1, 1));
        mx1 = fmaxf(mx1, __shfl_xor_sync(0xffffffffu, mx1, 2));

        float mn0 = fmaxf(m0v, mx0), mn1 = fmaxf(m1v, mx1);
        float f0 = ex2f((m0v - mn0) * C_EXP);
        float f1 = ex2f((m1v - mn1) * C_EXP);
        m0v = mn0; m1v = mn1;

        uint32_t P[16][2];
        float s0 = 0.f, s1 = 0.f;
#pragma unroll
        for (int ni = 0; ni < 16; ni++) {
            __half2 h0 = __floats2half2_rn((S[ni][0] - mn0) * C_EXP,
                                           (S[ni][1] - mn0) * C_EXP);
            __half2 h1 = __floats2half2_rn((S[ni][2] - mn1) * C_EXP,
                                           (S[ni][3] - mn1) * C_EXP);
            uint32_t p0 = ex2_f16x2(*(uint32_t*)&h0);
            uint32_t p1 = ex2_f16x2(*(uint32_t*)&h1);
            P[ni][0] = p0; P[ni][1] = p1;
            float2 q0f = __half22float2(*(__half2*)&p0);
            float2 q1f = __half22float2(*(__half2*)&p1);
            s0 += q0f.x + q0f.y;
            s1 += q1f.x + q1f.y;
        }
        s0 += __shfl_xor_sync(0xffffffffu, s0, 1);
        s0 += __shfl_xor_sync(0xffffffffu, s0, 2);
        s1 += __shfl_xor_sync(0xffffffffu, s1, 1);
        s1 += __shfl_xor_sync(0xffffffffu, s1, 2);
        l0 = l0 * f0 + s0;
        l1 = l1 * f1 + s1;

#pragma unroll
        for (int i = 0; i < 16; i++) {
            y[i][0] *= f0; y[i][1] *= f0;
            y[i][2] *= f1; y[i][3] *= f1;
        }

#pragma unroll
        for (int kc2 = 0; kc2 < 8; kc2++) {
            uint32_t a[4] = { P[2 * kc2][0], P[2 * kc2][1],
                              P[2 * kc2 + 1][0], P[2 * kc2 + 1][1] };
#pragma unroll
            for (int dj = 0; dj < 8; dj++) {
                uint32_t r0, r1, r2, r3;
                LDM4T(r0, r1, r2, r3,
                      sV + (dj >> 2) * 16384 +
                      tile_off(kc2 * 16 + l15, ((dj & 3) << 1) + lh));
                uint32_t b0[2] = { r0, r1 }, b1[2] = { r2, r3 };
                MMA16816(y[2 * dj], a, b0);
                MMA16816(y[2 * dj + 1], a, b1);
            }
        }
        __syncthreads();
    }

    // ===================== peeled diagonal tile (wid-bounded loops) ========
    {
        asm volatile("cp.async.wait_group 0;" ::: "memory");
        __syncthreads();

        const int t = nt - 1;
        uint32_t stg = sb + 32768 + (t & 1) * 65536;
        uint32_t sK = stg, sV = stg + 32768;
        const int k0 = t * 128;

        float S[16][4];
#pragma unroll
        for (int ni = 0; ni < 16; ni++)
#pragma unroll
            for (int q = 0; q < 4; q++) S[ni][q] = 0.f;

#pragma unroll
        for (int kc = 0; kc < 8; kc++) {
            uint32_t a[4];
            LDM4(a[0], a[1], a[2], a[3],
                 sQ + (kc >> 2) * 16384 + tile_off(mrow + l15, 2 * (kc & 3) + lh));
            for (int ng = 0; ng <= wid; ng++) {     // only needed col groups
                uint32_t r0, r1, r2, r3;
                LDM4(r0, r1, r2, r3,
                     sK + (kc >> 2) * 16384 +
                     tile_off(ng * 16 + ((bmat & 2) << 2) + br, 2 * (kc & 3) + (bmat & 1)));
                uint32_t b0[2] = { r0, r1 }, b1[2] = { r2, r3 };
                MMA16816(S[ng * 2], a, b0);
                MMA16816(S[ng * 2 + 1], a, b1);
            }
        }

        // causal mask (also -1e30 for the untouched ng > wid groups)
        {
            int row0 = q0 + mrow + tr, row1 = row0 + 8;
#pragma unroll
            for (int ni = 0; ni < 16; ni++) {
                int col = k0 + ni * 8 + 2 * tc;
                if (col > row0)     S[ni][0] = -1e30f;
                if (col + 1 > row0) S[ni][1] = -1e30f;
                if (col > row1)     S[ni][2] = -1e30f;
                if (col + 1 > row1) S[ni][3] = -1e30f;
            }
        }

        float mx0 = -1e30f, mx1 = -1e30f;
#pragma unroll
        for (int ni = 0; ni < 16; ni++) {
            mx0 = fmaxf(mx0, fmaxf(S[ni][0], S[ni][1]));
            mx1 = fmaxf(mx1, fmaxf(S[ni][2], S[ni][3]));
        }
        mx0 = fmaxf(mx0, __shfl_xor_sync(0xffffffffu, mx0, 1));
        mx0 = fmaxf(mx0, __shfl_xor_sync(0xffffffffu, mx0, 2));
        mx1 = fmaxf(mx1, __shfl_xor_sync(0xffffffffu, mx1, 1));
        mx1 = fmaxf(mx1, __shfl_xor_sync(0xffffffffu, mx1, 2));

        float mn0 = fmaxf(m0v, mx0), mn1 = fmaxf(m1v, mx1);
        float f0 = ex2f((m0v - mn0) * C_EXP);
        float f1 = ex2f((m1v - mn1) * C_EXP);

        uint32_t P[16][2];
        float s0 = 0.f, s1 = 0.f;
#pragma unroll
        for (int ni = 0; ni < 16; ni++) {
            __half2 h0 = __floats2half2_rn((S[ni][0] - mn0) * C_EXP,
                                           (S[ni][1] - mn0) * C_EXP);
            __half2 h1 = __floats2half2_rn((S[ni][2] - mn1) * C_EXP,
                                           (S[ni][3] - mn1) * C_EXP);
            uint32_t p0 = ex2_f16x2(*(uint32_t*)&h0);
            uint32_t p1 = ex2_f16x2(*(uint32_t*)&h1);
            P[ni][0] = p0; P[ni][1] = p1;
            float2 q0f = __half22float2(*(__half2*)&p0);
            float2 q1f = __half22float2(*(__half2*)&p1);
            s0 += q0f.x + q0f.y;
            s1 += q1f.x + q1f.y;
        }
        s0 += __shfl_xor_sync(0xffffffffu, s0, 1);
        s0 += __shfl_xor_sync(0xffffffffu, s0, 2);
        s1 += __shfl_xor_sync(0xffffffffu, s1, 1);
        s1 += __shfl_xor_sync(0xffffffffu, s1, 2);
        l0 = l0 * f0 + s0;
        l1 = l1 * f1 + s1;

#pragma unroll
        for (int i = 0; i < 16; i++) {
            y[i][0] *= f0; y[i][1] *= f0;
            y[i][2] *= f1; y[i][3] *= f1;
        }

        for (int kc2 = 0; kc2 <= wid; kc2++) {      // P rows beyond wid are 0
            uint32_t a[4] = { P[2 * kc2][0], P[2 * kc2][1],
                              P[2 * kc2 + 1][0], P[2 * kc2 + 1][1] };
#pragma unroll
            for (int dj = 0; dj < 8; dj++) {
                uint32_t r0, r1, r2, r3;
                LDM4T(r0, r1, r2, r3,
                      sV + (dj >> 2) * 16384 +
                      tile_off(kc2 * 16 + l15, ((dj & 3) << 1) + lh));
                uint32_t b0[2] = { r0, r1 }, b1[2] = { r2, r3 };
                MMA16816(y[2 * dj], a, b0);
                MMA16816(y[2 * dj + 1], a, b1);
            }
        }
    }

    float inv0 = 1.f / l0, inv1 = 1.f / l1;
#pragma unroll
    for (int ni = 0; ni < 16; ni++) {
        int col = h * HDIM + ni * 8 + 2 * tc;
        int row0 = q0 + mrow + tr;
        *(__half2*)(g_a16 + ((size_t)b * SS + row0) * HIDD + col) =
            __floats2half2_rn(y[ni][0] * inv0, y[ni][1] * inv0);
        *(__half2*)(g_a16 + ((size_t)b * SS + row0 + 8) * HIDD + col) =
            __floats2half2_rn(y[ni][2] * inv1, y[ni][3] * inv1);
    }
}

// ---------------------------------------------------------------------------
extern "C" void kernel_launch(void* const* d_in, const int* in_sizes, int n_in,
                              void* d_out, int out_size)
{
    const float* x    = (const float*)d_in[0];
    const float* cosb = (const float*)d_in[1];
    const float* sinb = (const float*)d_in[2];
    const float* Wq   = (const float*)d_in[3];
    const float* Wk   = (const float*)d_in[4];
    const float* Wv   = (const float*)d_in[5];
    const float* Wo   = (const float*)d_in[6];
    float* out = (float*)d_out;

    cudaFuncSetAttribute(flash16,
                         cudaFuncAttributeMaxDynamicSharedMemorySize, FLASH_SMEM);
    cudaFuncSetAttribute(gemm_f16<1>,
                         cudaFuncAttributeMaxDynamicSharedMemorySize, GEMM_SMEM);
    cudaFuncSetAttribute(gemm_f16<0>,
                         cudaFuncAttributeMaxDynamicSharedMemorySize, GEMM_SMEM);

    // Fused fp16 conversions (x + all weights)
    cvt_all<<<(CVT_Q + 255) / 256, 256>>>(x, Wq, Wk, Wv, Wo);

    // Fused QKV projection (+RoPE), fp16 outputs  (24 n-tiles x 32 m-tiles)
    gemm_f16<1><<<dim3(24, 32), 256, GEMM_SMEM>>>(nullptr, cosb, sinb);

    // Tensor-core flash attention (peeled diagonal tile)
    flash16<<<dim3(SS / 128, NHQ, BB), 256, FLASH_SMEM>>>();

    // Output projection (fp32 out)  (16 n-tiles x 32 m-tiles)
    gemm_f16<0><<<dim3(16, 32), 256, GEMM_SMEM>>>(out, nullptr, nullptr);
}